// round 14
// baseline (speedup 1.0000x reference)
#include <cuda_runtime.h>
#include <cuda_bf16.h>
#include <math.h>

// ---------------------------------------------------------------------------
// Problem constants
// ---------------------------------------------------------------------------
#define BB   4
#define SS   1024
#define DIN  58
#define DD   512
#define HH   8
#define HD   64          // DD/HH
#define FF_  2048
#define GG   32
#define NQ_  4
#define KK_  2048
#define DG_  16
#define NLAYERS 6
#define NTOK (BB*SS)     // 4096

// ---------------------------------------------------------------------------
// XLA:CPU vectorized fast exp — fused Cody-Waite + Horner (fast-math contracts
// VSL's mul+add into fmla on aarch64). Empirically the best-matching variant.
// ---------------------------------------------------------------------------
__device__ __forceinline__ float xla_expf(float x)
{
    x = fminf(x, 88.3762626647950f);
    x = fmaxf(x, -87.3365478515625f);
    float fx = fmaf(x, 1.44269504088896341f, 0.5f);
    fx = floorf(fx);
    x = fmaf(fx, -0.693359375f, x);
    x = fmaf(fx, 2.12194440e-4f, x);
    float z = x * x;
    float y = 1.9875691500E-4f;
    y = fmaf(y, x, 1.3981999507E-3f);
    y = fmaf(y, x, 8.3334519073E-3f);
    y = fmaf(y, x, 4.1665795894E-2f);
    y = fmaf(y, x, 1.6666665459E-1f);
    y = fmaf(y, x, 5.0000001201E-1f);
    y = fmaf(y, z, x);
    y = y + 1.0f;
    int n = (int)fx;
    return y * __int_as_float((n + 127) << 23);
}

// ---------------------------------------------------------------------------
// Scratch (device globals)
// ---------------------------------------------------------------------------
__device__ float g_X   [NTOK*DD];
__device__ float g_QKV [NTOK*3*DD];
__device__ float g_ATT [NTOK*DD];
__device__ float g_TMP [NTOK*DD];
__device__ float g_FFH [NTOK*FF_];
__device__ float g_VQR [NTOK*DD];
__device__ float g_QOUT[NTOK*DD];
__device__ float g_LOSSP[NTOK*GG];

// ---------------------------------------------------------------------------
// SGEMM, Eigen gebp semantics.
//   C[M,N] = op( [Cin +] sum_{k<K} A[.,k]B[k,.] [+ bias] )
// ADDC=1: accumulate into existing C (panel-boundary add, one rounding —
// exactly Eigen's "C += micro-panel accumulator").
// lda = row stride of A (full K of the logical matrix, >= K of this panel).
// ---------------------------------------------------------------------------
template<int RELU, int ADDC, int BIAS>
__global__ __launch_bounds__(256) void sgemm128(
    const float* __restrict__ A, const float* __restrict__ Bm,
    const float* __restrict__ bias, float* __restrict__ C,
    int M, int N, int K, int lda)
{
    __shared__ float As[8][128];
    __shared__ float Bs[8][128];

    const int tid = threadIdx.x;
    const int tx = tid & 15;
    const int ty = tid >> 4;
    const int m0 = blockIdx.y * 128;
    const int n0 = blockIdx.x * 128;

    const int arow = tid >> 1;
    const int acol = (tid & 1) * 4;
    const int brow = tid >> 5;
    const int bcol = (tid & 31) * 4;

    float acc[8][8];
#pragma unroll
    for (int i = 0; i < 8; i++)
#pragma unroll
        for (int j = 0; j < 8; j++) acc[i][j] = 0.0f;

    const float* Aptr = A + (size_t)(m0 + arow) * lda + acol;
    const float* Bptr = Bm + (size_t)brow * N + n0 + bcol;

    for (int kb = 0; kb < K; kb += 8) {
        float4 av = *(const float4*)(Aptr + kb);
        float4 bv = *(const float4*)(Bptr + (size_t)kb * N);
        As[acol + 0][arow] = av.x;
        As[acol + 1][arow] = av.y;
        As[acol + 2][arow] = av.z;
        As[acol + 3][arow] = av.w;
        *(float4*)&Bs[brow][bcol] = bv;
        __syncthreads();

#pragma unroll
        for (int kk = 0; kk < 8; kk++) {
            float4 a0 = *(float4*)&As[kk][ty * 8];
            float4 a1 = *(float4*)&As[kk][ty * 8 + 4];
            float4 b0 = *(float4*)&Bs[kk][tx * 8];
            float4 b1 = *(float4*)&Bs[kk][tx * 8 + 4];
            float ar[8] = {a0.x, a0.y, a0.z, a0.w, a1.x, a1.y, a1.z, a1.w};
            float br[8] = {b0.x, b0.y, b0.z, b0.w, b1.x, b1.y, b1.z, b1.w};
#pragma unroll
            for (int i = 0; i < 8; i++)
#pragma unroll
                for (int j = 0; j < 8; j++)
                    acc[i][j] = fmaf(ar[i], br[j], acc[i][j]);
        }
        __syncthreads();
    }

#pragma unroll
    for (int i = 0; i < 8; i++) {
        int row = m0 + ty * 8 + i;
        float* cp = C + (size_t)row * N + n0 + tx * 8;
        float out[8];
#pragma unroll
        for (int j = 0; j < 8; j++) {
            float v = acc[i][j];
            if (ADDC) v = __fadd_rn(cp[j], v);                  // panel add
            if (BIAS) v = __fadd_rn(v, bias[n0 + tx * 8 + j]);  // bias add
            if (RELU) v = fmaxf(v, 0.0f);
            out[j] = v;
        }
        float4 o0 = {out[0], out[1], out[2], out[3]};
        float4 o1 = {out[4], out[5], out[6], out[7]};
        *(float4*)cp = o0;
        *(float4*)(cp + 4) = o1;
    }
}

// ---------------------------------------------------------------------------
// Input projection + positional encoding
// ---------------------------------------------------------------------------
__global__ void inproj_pe(const float* __restrict__ bs, const float* __restrict__ W,
                          const float* __restrict__ b, float* __restrict__ out)
{
    int idx = blockIdx.x * blockDim.x + threadIdx.x;
    if (idx >= NTOK * DD) return;
    int row = idx / DD;
    int col = idx - row * DD;
    float s = 0.0f;
    const float* xr = bs + (size_t)row * DIN;
#pragma unroll 2
    for (int k = 0; k < DIN; k++)
        s = fmaf(xr[k], W[(size_t)k * DD + col], s);
    s = __fadd_rn(s, b[col]);

    int pos = row & (SS - 1);
    int i = col >> 1;
    const float c32 = (float)(-9.210340371976184 / 512.0);  // f32(-ln(10000)/512)
    float t   = __fmul_rn((float)(2 * i), c32);
    float dv  = xla_expf(t);
    float ang = __fmul_rn((float)pos, dv);
    float pe  = (col & 1) ? (float)cos((double)ang)
                          : (float)sin((double)ang);
    out[idx] = __fadd_rn(s, pe);
}

// ---------------------------------------------------------------------------
// Output projection
// ---------------------------------------------------------------------------
__global__ void outproj(const float* __restrict__ X, const float* __restrict__ W,
                        const float* __restrict__ b, float* __restrict__ out)
{
    int idx = blockIdx.x * blockDim.x + threadIdx.x;
    if (idx >= NTOK * DIN) return;
    int row = idx / DIN;
    int col = idx - row * DIN;
    float s = 0.0f;
    const float* xr = X + (size_t)row * DD;
#pragma unroll 4
    for (int k = 0; k < DD; k++)
        s = fmaf(xr[k], W[(size_t)k * DIN + col], s);
    out[idx] = __fadd_rn(s, b[col]);
}

// ---------------------------------------------------------------------------
// 3-pass attention (max, sequential ascending denominator, CR div + fma V acc)
// ---------------------------------------------------------------------------
__global__ __launch_bounds__(128) void attn_kernel(
    const float* __restrict__ qkv, float* __restrict__ out)
{
    const int tid = threadIdx.x;
    const int bh = blockIdx.y;
    const int b = bh >> 3;
    const int h = bh & 7;
    const int qs = blockIdx.x * 128 + tid;

    const float* base = qkv + (size_t)b * SS * (3 * DD);

    float q[HD];
    {
        const float* qp = base + (size_t)qs * (3 * DD) + h * HD;
#pragma unroll
        for (int d4 = 0; d4 < HD; d4 += 4) {
            float4 t = *(const float4*)(qp + d4);
            q[d4+0] = t.x; q[d4+1] = t.y; q[d4+2] = t.z; q[d4+3] = t.w;
        }
    }

    __shared__ float Ks[64][64];
    __shared__ float Vs[64][64];

    float m = -3.4e38f;
    for (int kt = 0; kt < SS / 64; kt++) {
#pragma unroll
        for (int r8 = 0; r8 < 8; r8++) {
            int idx = tid + r8 * 128;
            int krow = idx >> 4;
            int c4 = (idx & 15) * 4;
            const float* kp = base + (size_t)(kt * 64 + krow) * (3 * DD) + DD + h * HD + c4;
            *(float4*)&Ks[krow][c4] = *(const float4*)kp;
        }
        __syncthreads();
        for (int j = 0; j < 64; j++) {
            float s = 0.0f;
#pragma unroll
            for (int d = 0; d < HD; d++)
                s = fmaf(q[d], Ks[j][d], s);
            s = __fmul_rn(s, 0.125f);
            m = fmaxf(m, s);
        }
        __syncthreads();
    }

    float l = 0.0f;
    for (int kt = 0; kt < SS / 64; kt++) {
#pragma unroll
        for (int r8 = 0; r8 < 8; r8++) {
            int idx = tid + r8 * 128;
            int krow = idx >> 4;
            int c4 = (idx & 15) * 4;
            const float* kp = base + (size_t)(kt * 64 + krow) * (3 * DD) + DD + h * HD + c4;
            *(float4*)&Ks[krow][c4] = *(const float4*)kp;
        }
        __syncthreads();
        for (int j = 0; j < 64; j++) {
            float s = 0.0f;
#pragma unroll
            for (int d = 0; d < HD; d++)
                s = fmaf(q[d], Ks[j][d], s);
            s = __fmul_rn(s, 0.125f);
            l = __fadd_rn(l, xla_expf(__fsub_rn(s, m)));
        }
        __syncthreads();
    }

    float o[HD];
#pragma unroll
    for (int d = 0; d < HD; d++) o[d] = 0.0f;

    for (int kt = 0; kt < SS / 64; kt++) {
#pragma unroll
        for (int r8 = 0; r8 < 8; r8++) {
            int idx = tid + r8 * 128;
            int krow = idx >> 4;
            int c4 = (idx & 15) * 4;
            const float* kp = base + (size_t)(kt * 64 + krow) * (3 * DD) + DD + h * HD + c4;
            const float* vp = base + (size_t)(kt * 64 + krow) * (3 * DD) + 2 * DD + h * HD + c4;
            *(float4*)&Ks[krow][c4] = *(const float4*)kp;
            *(float4*)&Vs[krow][c4] = *(const float4*)vp;
        }
        __syncthreads();
        for (int j = 0; j < 64; j++) {
            float s = 0.0f;
#pragma unroll
            for (int d = 0; d < HD; d++)
                s = fmaf(q[d], Ks[j][d], s);
            s = __fmul_rn(s, 0.125f);
            float p = __fdiv_rn(xla_expf(__fsub_rn(s, m)), l);
#pragma unroll
            for (int d = 0; d < HD; d++)
                o[d] = fmaf(p, Vs[j][d], o[d]);
        }
        __syncthreads();
    }

    float* op = out + (size_t)(b * SS + qs) * DD + h * HD;
#pragma unroll
    for (int d4 = 0; d4 < HD; d4 += 4) {
        float4 t;
        t.x = o[d4+0]; t.y = o[d4+1]; t.z = o[d4+2]; t.w = o[d4+3];
        *(float4*)(op + d4) = t;
    }
}

// ---------------------------------------------------------------------------
// LayerNorm(x + a) in place. Sequential ascending mean/var (bit-identical to
// the 4-/16-partial variants per R9/R10/R13); CR 1/sqrt.
// ---------------------------------------------------------------------------
__global__ __launch_bounds__(128) void ln_add(
    float* __restrict__ x, const float* __restrict__ a,
    const float* __restrict__ g, const float* __restrict__ bb)
{
    const int row = blockIdx.x;
    const int tid = threadIdx.x;
    __shared__ float v[DD];
    __shared__ float stat[2];

    for (int i = 0; i < 4; i++) {
        int c = tid + i * 128;
        v[c] = __fadd_rn(x[(size_t)row * DD + c], a[(size_t)row * DD + c]);
    }
    __syncthreads();

    if (tid == 0) {
        float s = 0.0f;
        for (int j = 0; j < DD; j++)
            s = __fadd_rn(s, v[j]);
        float mu = __fmul_rn(s, 1.0f / DD);
        float s2 = 0.0f;
        for (int j = 0; j < DD; j++) {
            float d = __fsub_rn(v[j], mu);
            s2 = __fadd_rn(s2, __fmul_rn(d, d));
        }
        stat[0] = mu;
        stat[1] = __fmul_rn(s2, 1.0f / DD);
    }
    __syncthreads();
    float mu = stat[0];
    float rs = __fdiv_rn(1.0f, __fsqrt_rn(__fadd_rn(stat[1], 1e-5f)));

    for (int i = 0; i < 4; i++) {
        int c = tid + i * 128;
        float t = __fmul_rn(__fmul_rn(__fsub_rn(v[c], mu), rs), g[c]);
        x[(size_t)row * DD + c] = __fadd_rn(t, bb[c]);
    }
}

// ---------------------------------------------------------------------------
// misc
// ---------------------------------------------------------------------------
__global__ void zero_kernel(float* __restrict__ p, int n)
{
    int i = blockIdx.x * blockDim.x + threadIdx.x;
    if (i < n) p[i] = 0.0f;
}
__global__ void copy_kernel(float* __restrict__ dst, const float* __restrict__ src, int n)
{
    int i = blockIdx.x * blockDim.x + threadIdx.x;
    if (i < n) dst[i] = src[i];
}

// ---------------------------------------------------------------------------
// One residual-VQ stage. d2 = (|r|^2 - 2*dot) + |c|^2
// ---------------------------------------------------------------------------
__global__ __launch_bounds__(256) void vq_step(
    const float* __restrict__ cb, float* __restrict__ r,
    float* __restrict__ qout, float* __restrict__ lossp, int qi)
{
    int warp = (blockIdx.x * blockDim.x + threadIdx.x) >> 5;
    int lane = threadIdx.x & 31;
    if (warp >= NTOK * GG) return;
    int t = warp >> 5;
    int g = warp & 31;

    float rv[DG_];
    float* rp = r + (size_t)t * DD + g * DG_;
#pragma unroll
    for (int d = 0; d < DG_; d++) rv[d] = rp[d];

    float s_r = 0.0f;
#pragma unroll
    for (int d = 0; d < DG_; d++)
        s_r = __fadd_rn(s_r, __fmul_rn(rv[d], rv[d]));

    const float* cbase = cb + ((size_t)(g * NQ_ + qi)) * KK_ * DG_;

    float best = 3.4e38f;
    int bi = 0;
    for (int i = 0; i < KK_ / 32; i++) {
        int k = lane + i * 32;
        const float* c = cbase + (size_t)k * DG_;
        float cv[DG_];
        float4 t0 = *(const float4*)(c + 0);
        float4 t1 = *(const float4*)(c + 4);
        float4 t2 = *(const float4*)(c + 8);
        float4 t3 = *(const float4*)(c + 12);
        cv[0]=t0.x; cv[1]=t0.y; cv[2]=t0.z; cv[3]=t0.w;
        cv[4]=t1.x; cv[5]=t1.y; cv[6]=t1.z; cv[7]=t1.w;
        cv[8]=t2.x; cv[9]=t2.y; cv[10]=t2.z; cv[11]=t2.w;
        cv[12]=t3.x; cv[13]=t3.y; cv[14]=t3.z; cv[15]=t3.w;

        float dot = 0.0f;
#pragma unroll
        for (int d = 0; d < DG_; d++)
            dot = fmaf(rv[d], cv[d], dot);

        float scb = 0.0f;
#pragma unroll
        for (int d = 0; d < DG_; d++)
            scb = __fadd_rn(scb, __fmul_rn(cv[d], cv[d]));

        float d2 = __fadd_rn(__fsub_rn(s_r, __fmul_rn(2.0f, dot)), scb);
        if (d2 < best) { best = d2; bi = k; }
    }
#pragma unroll
    for (int off = 16; off > 0; off >>= 1) {
        float ob = __shfl_xor_sync(0xffffffffu, best, off);
        int   oi = __shfl_xor_sync(0xffffffffu, bi, off);
        if (ob < best || (ob == best && oi < bi)) { best = ob; bi = oi; }
    }

    const float* c = cbase + (size_t)bi * DG_;
    float err = 0.0f;
    if (lane < DG_) {
        float cv  = c[lane];
        float rvv = rv[lane];
        float df  = __fsub_rn(cv, rvv);                   // quant - r
        err = __fmul_rn(df, df);
        size_t qidx = (size_t)t * DD + g * DG_ + lane;
        float qold = qout[qidx];
        qout[qidx] = __fadd_rn(__fadd_rn(qold, rvv), df); // ((q + r) + (quant - r))
        rp[lane] = __fsub_rn(rvv, cv);                    // r - quant
    }
#pragma unroll
    for (int off = 8; off > 0; off >>= 1)
        err += __shfl_xor_sync(0xffffffffu, err, off);
    if (lane == 0) lossp[warp] += err;
}

// ---------------------------------------------------------------------------
// Deterministic loss reduce
// ---------------------------------------------------------------------------
__global__ void loss_reduce(const float* __restrict__ lp, float* __restrict__ out)
{
    __shared__ float red[256];
    int tid = threadIdx.x;
    float s = 0.0f;
    for (int i = tid; i < NTOK * GG; i += 256) s += lp[i];
    red[tid] = s;
    __syncthreads();
    for (int o = 128; o > 0; o >>= 1) {
        if (tid < o) red[tid] += red[tid + o];
        __syncthreads();
    }
    if (tid == 0)
        out[0] = 0.1f * red[0] / 2097152.0f;   // B*S*G*DG
}

// ---------------------------------------------------------------------------
// Host orchestration
// ---------------------------------------------------------------------------
struct BlockParams {
    const float *qkv_w, *qkv_b, *out_w, *out_b, *ln1_g, *ln1_b;
    const float *ff1_w, *ff1_b, *ff2_w, *ff2_b, *ln2_g, *ln2_b;
};

static void run_block(float* X, float* QKV, float* ATT, float* TMP, float* FFH,
                      const BlockParams& p)
{
    for (int i = 0; i < NLAYERS; i++) {
        sgemm128<0,0,1><<<dim3(12, 32), 256>>>(X, p.qkv_w + (size_t)i * DD * 3 * DD,
                                               p.qkv_b + (size_t)i * 3 * DD, QKV,
                                               NTOK, 3 * DD, DD, DD);
        attn_kernel<<<dim3(SS / 128, BB * HH), 128>>>(QKV, ATT);
        sgemm128<0,0,1><<<dim3(4, 32), 256>>>(ATT, p.out_w + (size_t)i * DD * DD,
                                              p.out_b + (size_t)i * DD, TMP,
                                              NTOK, DD, DD, DD);
        ln_add<<<NTOK, 128>>>(X, TMP, p.ln1_g + (size_t)i * DD, p.ln1_b + (size_t)i * DD);
        sgemm128<1,0,1><<<dim3(16, 32), 256>>>(X, p.ff1_w + (size_t)i * DD * FF_,
                                               p.ff1_b + (size_t)i * FF_, FFH,
                                               NTOK, FF_, DD, DD);
        // ff2: K=2048 -> Eigen kc panels of 1024: C = ((p1 + p2) + bias)
        sgemm128<0,0,0><<<dim3(4, 32), 256>>>(FFH, p.ff2_w + (size_t)i * FF_ * DD,
                                              p.ff2_b + (size_t)i * DD, TMP,
                                              NTOK, DD, 1024, FF_);
        sgemm128<0,1,1><<<dim3(4, 32), 256>>>(FFH + 1024,
                                              p.ff2_w + (size_t)i * FF_ * DD + (size_t)1024 * DD,
                                              p.ff2_b + (size_t)i * DD, TMP,
                                              NTOK, DD, 1024, FF_);
        ln_add<<<NTOK, 128>>>(X, TMP, p.ln2_g + (size_t)i * DD, p.ln2_b + (size_t)i * DD);
    }
}

extern "C" void kernel_launch(void* const* d_in, const int* in_sizes, int n_in,
                              void* d_out, int out_size)
{
    const float* blendshapes = (const float*)d_in[0];
    const float* w_in  = (const float*)d_in[1];
    const float* b_in  = (const float*)d_in[2];

    BlockParams enc, dec;
    enc.qkv_w = (const float*)d_in[3];  enc.qkv_b = (const float*)d_in[4];
    enc.out_w = (const float*)d_in[5];  enc.out_b = (const float*)d_in[6];
    enc.ln1_g = (const float*)d_in[7];  enc.ln1_b = (const float*)d_in[8];
    enc.ff1_w = (const float*)d_in[9];  enc.ff1_b = (const float*)d_in[10];
    enc.ff2_w = (const float*)d_in[11]; enc.ff2_b = (const float*)d_in[12];
    enc.ln2_g = (const float*)d_in[13]; enc.ln2_b = (const float*)d_in[14];
    dec.qkv_w = (const float*)d_in[15]; dec.qkv_b = (const float*)d_in[16];
    dec.out_w = (const float*)d_in[17]; dec.out_b = (const float*)d_in[18];
    dec.ln1_g = (const float*)d_in[19]; dec.ln1_b = (const float*)d_in[20];
    dec.ff1_w = (const float*)d_in[21]; dec.ff1_b = (const float*)d_in[22];
    dec.ff2_w = (const float*)d_in[23]; dec.ff2_b = (const float*)d_in[24];
    dec.ln2_g = (const float*)d_in[25]; dec.ln2_b = (const float*)d_in[26];
    const float* codebooks = (const float*)d_in[27];
    const float* w_out = (const float*)d_in[28];
    const float* b_out = (const float*)d_in[29];

    float *X, *QKV, *ATT, *TMP, *FFH, *VQR, *QOUT, *LOSSP;
    cudaGetSymbolAddress((void**)&X,    g_X);
    cudaGetSymbolAddress((void**)&QKV,  g_QKV);
    cudaGetSymbolAddress((void**)&ATT,  g_ATT);
    cudaGetSymbolAddress((void**)&TMP,  g_TMP);
    cudaGetSymbolAddress((void**)&FFH,  g_FFH);
    cudaGetSymbolAddress((void**)&VQR,  g_VQR);
    cudaGetSymbolAddress((void**)&QOUT, g_QOUT);
    cudaGetSymbolAddress((void**)&LOSSP,g_LOSSP);

    // 1. Input projection + positional encoding
    inproj_pe<<<(NTOK * DD + 255) / 256, 256>>>(blendshapes, w_in, b_in, X);

    // 2. Encoder
    run_block(X, QKV, ATT, TMP, FFH, enc);

    // 3. Grouped residual VQ
    copy_kernel<<<(NTOK * DD + 255) / 256, 256>>>(VQR, X, NTOK * DD);
    zero_kernel<<<(NTOK * DD + 255) / 256, 256>>>(QOUT, NTOK * DD);
    zero_kernel<<<(NTOK * GG + 255) / 256, 256>>>(LOSSP, NTOK * GG);
    for (int qi = 0; qi < NQ_; qi++)
        vq_step<<<(NTOK * GG * 32 + 255) / 256, 256>>>(codebooks, VQR, QOUT, LOSSP, qi);

    // 4. Decoder
    run_block(QOUT, QKV, ATT, TMP, FFH, dec);

    // 5. Output projection + loss
    float* out = (float*)d_out;
    outproj<<<(NTOK * DIN + 127) / 128, 128>>>(QOUT, w_out, b_out, out);
    loss_reduce<<<1, 256>>>(LOSSP, out + (out_size - 1));
}

// round 15
// speedup vs baseline: 1.3525x; 1.3525x over previous
#include <cuda_runtime.h>
#include <cuda_bf16.h>
#include <math.h>

// ---------------------------------------------------------------------------
// Problem constants
// ---------------------------------------------------------------------------
#define BB   4
#define SS   1024
#define DIN  58
#define DD   512
#define HH   8
#define HD   64          // DD/HH
#define FF_  2048
#define GG   32
#define NQ_  4
#define KK_  2048
#define DG_  16
#define NLAYERS 6
#define NTOK (BB*SS)     // 4096

// ---------------------------------------------------------------------------
// XLA:CPU vectorized fast exp — fused Cody-Waite + Horner (FROZEN: part of the
// passing numerics recipe).
// ---------------------------------------------------------------------------
__device__ __forceinline__ float xla_expf(float x)
{
    x = fminf(x, 88.3762626647950f);
    x = fmaxf(x, -87.3365478515625f);
    float fx = fmaf(x, 1.44269504088896341f, 0.5f);
    fx = floorf(fx);
    x = fmaf(fx, -0.693359375f, x);
    x = fmaf(fx, 2.12194440e-4f, x);
    float z = x * x;
    float y = 1.9875691500E-4f;
    y = fmaf(y, x, 1.3981999507E-3f);
    y = fmaf(y, x, 8.3334519073E-3f);
    y = fmaf(y, x, 4.1665795894E-2f);
    y = fmaf(y, x, 1.6666665459E-1f);
    y = fmaf(y, x, 5.0000001201E-1f);
    y = fmaf(y, z, x);
    y = y + 1.0f;
    int n = (int)fx;
    return y * __int_as_float((n + 127) << 23);
}

// ---------------------------------------------------------------------------
// Scratch (device globals)
// ---------------------------------------------------------------------------
__device__ float g_X   [NTOK*DD];
__device__ float g_QKV [NTOK*3*DD];
__device__ float g_ATT [NTOK*DD];
__device__ float g_TMP [NTOK*DD];
__device__ float g_FFH [NTOK*FF_];
__device__ float g_VQR [NTOK*DD];
__device__ float g_QOUT[NTOK*DD];
__device__ float g_LOSSP[NTOK*GG];
__device__ float g_SC  [(size_t)BB*HH*SS*SS];   // attention scores/probs, 134MB

// ---------------------------------------------------------------------------
// SGEMM 128x128, DOUBLE-BUFFERED. Per-element math identical to the passing
// kernel: single accumulator, ascending-k fmaf chain; epilogue op order kept.
// ---------------------------------------------------------------------------
template<int RELU, int ADDC, int BIAS>
__global__ __launch_bounds__(256) void sgemm_n128(
    const float* __restrict__ A, const float* __restrict__ Bm,
    const float* __restrict__ bias, float* __restrict__ C,
    int M, int N, int K, int lda)
{
    __shared__ float As[2][8][128];
    __shared__ float Bs[2][8][128];

    const int tid = threadIdx.x;
    const int tx = tid & 15;
    const int ty = tid >> 4;
    const int m0 = blockIdx.y * 128;
    const int n0 = blockIdx.x * 128;

    const int arow = tid >> 1;
    const int acol = (tid & 1) * 4;
    const int brow = tid >> 5;
    const int bcol = (tid & 31) * 4;

    float acc[8][8];
#pragma unroll
    for (int i = 0; i < 8; i++)
#pragma unroll
        for (int j = 0; j < 8; j++) acc[i][j] = 0.0f;

    const float* Aptr = A + (size_t)(m0 + arow) * lda + acol;
    const float* Bptr = Bm + (size_t)brow * N + n0 + bcol;

    // preload first tile
    {
        float4 av = *(const float4*)(Aptr);
        float4 bv = *(const float4*)(Bptr);
        As[0][acol + 0][arow] = av.x;
        As[0][acol + 1][arow] = av.y;
        As[0][acol + 2][arow] = av.z;
        As[0][acol + 3][arow] = av.w;
        *(float4*)&Bs[0][brow][bcol] = bv;
    }
    __syncthreads();

    int buf = 0;
    for (int kb = 0; kb < K; kb += 8) {
        const bool has_next = (kb + 8 < K);
        float4 avn, bvn;
        if (has_next) {
            avn = *(const float4*)(Aptr + kb + 8);
            bvn = *(const float4*)(Bptr + (size_t)(kb + 8) * N);
        }
#pragma unroll
        for (int kk = 0; kk < 8; kk++) {
            float4 a0 = *(float4*)&As[buf][kk][ty * 8];
            float4 a1 = *(float4*)&As[buf][kk][ty * 8 + 4];
            float4 b0 = *(float4*)&Bs[buf][kk][tx * 8];
            float4 b1 = *(float4*)&Bs[buf][kk][tx * 8 + 4];
            float ar[8] = {a0.x, a0.y, a0.z, a0.w, a1.x, a1.y, a1.z, a1.w};
            float br[8] = {b0.x, b0.y, b0.z, b0.w, b1.x, b1.y, b1.z, b1.w};
#pragma unroll
            for (int i = 0; i < 8; i++)
#pragma unroll
                for (int j = 0; j < 8; j++)
                    acc[i][j] = fmaf(ar[i], br[j], acc[i][j]);
        }
        if (has_next) {
            int nb = buf ^ 1;
            As[nb][acol + 0][arow] = avn.x;
            As[nb][acol + 1][arow] = avn.y;
            As[nb][acol + 2][arow] = avn.z;
            As[nb][acol + 3][arow] = avn.w;
            *(float4*)&Bs[nb][brow][bcol] = bvn;
            __syncthreads();
            buf = nb;
        }
    }

#pragma unroll
    for (int i = 0; i < 8; i++) {
        int row = m0 + ty * 8 + i;
        float* cp = C + (size_t)row * N + n0 + tx * 8;
        float out[8];
#pragma unroll
        for (int j = 0; j < 8; j++) {
            float v = acc[i][j];
            if (ADDC) v = __fadd_rn(cp[j], v);
            if (BIAS) v = __fadd_rn(v, bias[n0 + tx * 8 + j]);
            if (RELU) v = fmaxf(v, 0.0f);
            out[j] = v;
        }
        float4 o0 = {out[0], out[1], out[2], out[3]};
        float4 o1 = {out[4], out[5], out[6], out[7]};
        *(float4*)cp = o0;
        *(float4*)(cp + 4) = o1;
    }
}

// ---------------------------------------------------------------------------
// SGEMM 128x64, DOUBLE-BUFFERED (for N=512 outputs: more blocks, lower regs).
// Same ascending-k fmaf chain + epilogue order.
// ---------------------------------------------------------------------------
template<int RELU, int ADDC, int BIAS>
__global__ __launch_bounds__(256) void sgemm_n64(
    const float* __restrict__ A, const float* __restrict__ Bm,
    const float* __restrict__ bias, float* __restrict__ C,
    int M, int N, int K, int lda)
{
    __shared__ float As[2][8][128];
    __shared__ float Bs[2][8][64];

    const int tid = threadIdx.x;
    const int tx = tid & 15;          // 16 col groups x 4
    const int ty = tid >> 4;          // 16 row groups x 8
    const int m0 = blockIdx.y * 128;
    const int n0 = blockIdx.x * 64;

    const int arow = tid >> 1;
    const int acol = (tid & 1) * 4;
    const int brow = tid >> 4;        // 0..7 (tid<128)
    const int bcol = (tid & 15) * 4;  // 0..60

    float acc[8][4];
#pragma unroll
    for (int i = 0; i < 8; i++)
#pragma unroll
        for (int j = 0; j < 4; j++) acc[i][j] = 0.0f;

    const float* Aptr = A + (size_t)(m0 + arow) * lda + acol;
    const float* Bptr = Bm + (size_t)brow * N + n0 + bcol;

    {
        float4 av = *(const float4*)(Aptr);
        As[0][acol + 0][arow] = av.x;
        As[0][acol + 1][arow] = av.y;
        As[0][acol + 2][arow] = av.z;
        As[0][acol + 3][arow] = av.w;
        if (tid < 128) {
            float4 bv = *(const float4*)(Bptr);
            *(float4*)&Bs[0][brow][bcol] = bv;
        }
    }
    __syncthreads();

    int buf = 0;
    for (int kb = 0; kb < K; kb += 8) {
        const bool has_next = (kb + 8 < K);
        float4 avn, bvn;
        if (has_next) {
            avn = *(const float4*)(Aptr + kb + 8);
            if (tid < 128)
                bvn = *(const float4*)(Bptr + (size_t)(kb + 8) * N);
        }
#pragma unroll
        for (int kk = 0; kk < 8; kk++) {
            float4 a0 = *(float4*)&As[buf][kk][ty * 8];
            float4 a1 = *(float4*)&As[buf][kk][ty * 8 + 4];
            float4 b0 = *(float4*)&Bs[buf][kk][tx * 4];
            float ar[8] = {a0.x, a0.y, a0.z, a0.w, a1.x, a1.y, a1.z, a1.w};
            float br[4] = {b0.x, b0.y, b0.z, b0.w};
#pragma unroll
            for (int i = 0; i < 8; i++)
#pragma unroll
                for (int j = 0; j < 4; j++)
                    acc[i][j] = fmaf(ar[i], br[j], acc[i][j]);
        }
        if (has_next) {
            int nb = buf ^ 1;
            As[nb][acol + 0][arow] = avn.x;
            As[nb][acol + 1][arow] = avn.y;
            As[nb][acol + 2][arow] = avn.z;
            As[nb][acol + 3][arow] = avn.w;
            if (tid < 128)
                *(float4*)&Bs[nb][brow][bcol] = bvn;
            __syncthreads();
            buf = nb;
        }
    }

#pragma unroll
    for (int i = 0; i < 8; i++) {
        int row = m0 + ty * 8 + i;
        float* cp = C + (size_t)row * N + n0 + tx * 4;
        float out[4];
#pragma unroll
        for (int j = 0; j < 4; j++) {
            float v = acc[i][j];
            if (ADDC) v = __fadd_rn(cp[j], v);
            if (BIAS) v = __fadd_rn(v, bias[n0 + tx * 4 + j]);
            if (RELU) v = fmaxf(v, 0.0f);
            out[j] = v;
        }
        float4 o0 = {out[0], out[1], out[2], out[3]};
        *(float4*)cp = o0;
    }
}

// ---------------------------------------------------------------------------
// Attention scores: SC[bh][q][k] = (Q[q]·K[k]) * 0.125, ascending-d fmaf chain
// (bit-identical to the passing 3-pass kernel's score computation).
// grid: (k-tile 8, q-tile 8, bh 32), 256 threads, 128x128 tile, K=64.
// ---------------------------------------------------------------------------
__global__ __launch_bounds__(256) void attn_scores(
    const float* __restrict__ qkv, float* __restrict__ sc)
{
    const int bh = blockIdx.z;
    const int b = bh >> 3;
    const int h = bh & 7;
    const float* base = qkv + (size_t)b * SS * (3 * DD);
    const int q0 = blockIdx.y * 128;
    const int k0 = blockIdx.x * 128;

    __shared__ float Qs[8][128];
    __shared__ float Ks[8][128];

    const int tid = threadIdx.x;
    const int tx = tid & 15;
    const int ty = tid >> 4;
    const int arow = tid >> 1;
    const int acol = (tid & 1) * 4;

    float acc[8][8];
#pragma unroll
    for (int i = 0; i < 8; i++)
#pragma unroll
        for (int j = 0; j < 8; j++) acc[i][j] = 0.0f;

    for (int kb = 0; kb < HD; kb += 8) {
        float4 qa = *(const float4*)(base + (size_t)(q0 + arow) * (3 * DD) + h * HD + kb + acol);
        float4 ka = *(const float4*)(base + (size_t)(k0 + arow) * (3 * DD) + DD + h * HD + kb + acol);
        Qs[acol + 0][arow] = qa.x;
        Qs[acol + 1][arow] = qa.y;
        Qs[acol + 2][arow] = qa.z;
        Qs[acol + 3][arow] = qa.w;
        Ks[acol + 0][arow] = ka.x;
        Ks[acol + 1][arow] = ka.y;
        Ks[acol + 2][arow] = ka.z;
        Ks[acol + 3][arow] = ka.w;
        __syncthreads();
#pragma unroll
        for (int kk = 0; kk < 8; kk++) {
            float4 a0 = *(float4*)&Qs[kk][ty * 8];
            float4 a1 = *(float4*)&Qs[kk][ty * 8 + 4];
            float4 b0 = *(float4*)&Ks[kk][tx * 8];
            float4 b1 = *(float4*)&Ks[kk][tx * 8 + 4];
            float ar[8] = {a0.x, a0.y, a0.z, a0.w, a1.x, a1.y, a1.z, a1.w};
            float br[8] = {b0.x, b0.y, b0.z, b0.w, b1.x, b1.y, b1.z, b1.w};
#pragma unroll
            for (int i = 0; i < 8; i++)
#pragma unroll
                for (int j = 0; j < 8; j++)
                    acc[i][j] = fmaf(ar[i], br[j], acc[i][j]);
        }
        __syncthreads();
    }

    float* out = sc + ((size_t)bh * SS + q0) * SS + k0;
#pragma unroll
    for (int i = 0; i < 8; i++) {
        float* op = out + (size_t)(ty * 8 + i) * SS + tx * 8;
        float4 o0, o1;
        o0.x = __fmul_rn(acc[i][0], 0.125f);
        o0.y = __fmul_rn(acc[i][1], 0.125f);
        o0.z = __fmul_rn(acc[i][2], 0.125f);
        o0.w = __fmul_rn(acc[i][3], 0.125f);
        o1.x = __fmul_rn(acc[i][4], 0.125f);
        o1.y = __fmul_rn(acc[i][5], 0.125f);
        o1.z = __fmul_rn(acc[i][6], 0.125f);
        o1.w = __fmul_rn(acc[i][7], 0.125f);
        *(float4*)op = o0;
        *(float4*)(op + 4) = o1;
    }
}

// ---------------------------------------------------------------------------
// Softmax rows in place: p = xla_expf(s - max) / sum. Max exact; sum via block
// tree (reduce order proven flip-neutral R9/R10/R13). grid (SS, B*H), 256 thr.
// ---------------------------------------------------------------------------
__global__ __launch_bounds__(256) void attn_softmax(float* __restrict__ sc)
{
    const int row = blockIdx.x;
    const int bh = blockIdx.y;
    float* p = sc + ((size_t)bh * SS + row) * SS;

    __shared__ float e[SS];
    __shared__ float red[256];
    const int tid = threadIdx.x;

    float m = -3.4e38f;
    for (int i = tid; i < SS; i += 256)
        m = fmaxf(m, p[i]);
    red[tid] = m;
    __syncthreads();
    for (int o = 128; o > 0; o >>= 1) {
        if (tid < o) red[tid] = fmaxf(red[tid], red[tid + o]);
        __syncthreads();
    }
    m = red[0];
    __syncthreads();

    float s = 0.0f;
    for (int i = tid; i < SS; i += 256) {
        float ev = xla_expf(__fsub_rn(p[i], m));
        e[i] = ev;
        s = __fadd_rn(s, ev);
    }
    red[tid] = s;
    __syncthreads();
    for (int o = 128; o > 0; o >>= 1) {
        if (tid < o) red[tid] = __fadd_rn(red[tid], red[tid + o]);
        __syncthreads();
    }
    float l = red[0];

    for (int i = tid; i < SS; i += 256)
        p[i] = __fdiv_rn(e[i], l);
}

// ---------------------------------------------------------------------------
// attn_av: ATT[q, h*64+d] = sum_j P[q][j] * V[j][d], ascending-j fmaf chain
// (bit-identical to the passing pass-3 accumulation). 128x64 tile, K=1024,
// double buffered. grid (q-tile 8, bh 32), 256 threads.
// ---------------------------------------------------------------------------
__global__ __launch_bounds__(256) void attn_av(
    const float* __restrict__ sc, const float* __restrict__ qkv,
    float* __restrict__ out)
{
    const int bh = blockIdx.y;
    const int b = bh >> 3;
    const int h = bh & 7;
    const float* P = sc + (size_t)bh * SS * SS;
    const float* vbase = qkv + (size_t)b * SS * (3 * DD) + 2 * DD + h * HD;
    const int q0 = blockIdx.x * 128;

    __shared__ float As[2][8][128];
    __shared__ float Bs[2][8][64];

    const int tid = threadIdx.x;
    const int tx = tid & 15;
    const int ty = tid >> 4;
    const int arow = tid >> 1;
    const int acol = (tid & 1) * 4;
    const int brow = tid >> 4;
    const int bcol = (tid & 15) * 4;

    float acc[8][4];
#pragma unroll
    for (int i = 0; i < 8; i++)
#pragma unroll
        for (int j = 0; j < 4; j++) acc[i][j] = 0.0f;

    const float* Aptr = P + (size_t)(q0 + arow) * SS + acol;

    {
        float4 av = *(const float4*)(Aptr);
        As[0][acol + 0][arow] = av.x;
        As[0][acol + 1][arow] = av.y;
        As[0][acol + 2][arow] = av.z;
        As[0][acol + 3][arow] = av.w;
        if (tid < 128) {
            float4 bv = *(const float4*)(vbase + (size_t)brow * (3 * DD) + bcol);
            *(float4*)&Bs[0][brow][bcol] = bv;
        }
    }
    __syncthreads();

    int buf = 0;
    for (int kb = 0; kb < SS; kb += 8) {
        const bool has_next = (kb + 8 < SS);
        float4 avn, bvn;
        if (has_next) {
            avn = *(const float4*)(Aptr + kb + 8);
            if (tid < 128)
                bvn = *(const float4*)(vbase + (size_t)(kb + 8 + brow) * (3 * DD) + bcol);
        }
#pragma unroll
        for (int kk = 0; kk < 8; kk++) {
            float4 a0 = *(float4*)&As[buf][kk][ty * 8];
            float4 a1 = *(float4*)&As[buf][kk][ty * 8 + 4];
            float4 b0 = *(float4*)&Bs[buf][kk][tx * 4];
            float ar[8] = {a0.x, a0.y, a0.z, a0.w, a1.x, a1.y, a1.z, a1.w};
            float br[4] = {b0.x, b0.y, b0.z, b0.w};
#pragma unroll
            for (int i = 0; i < 8; i++)
#pragma unroll
                for (int j = 0; j < 4; j++)
                    acc[i][j] = fmaf(ar[i], br[j], acc[i][j]);
        }
        if (has_next) {
            int nb = buf ^ 1;
            As[nb][acol + 0][arow] = avn.x;
            As[nb][acol + 1][arow] = avn.y;
            As[nb][acol + 2][arow] = avn.z;
            As[nb][acol + 3][arow] = avn.w;
            if (tid < 128)
                *(float4*)&Bs[nb][brow][bcol] = bvn;
            __syncthreads();
            buf = nb;
        }
    }

#pragma unroll
    for (int i = 0; i < 8; i++) {
        int q = q0 + ty * 8 + i;
        float* op = out + (size_t)(b * SS + q) * DD + h * HD + tx * 4;
        float4 o0 = {acc[i][0], acc[i][1], acc[i][2], acc[i][3]};
        *(float4*)op = o0;
    }
}

// ---------------------------------------------------------------------------
// Input projection + positional encoding (unchanged — frozen numerics)
// ---------------------------------------------------------------------------
__global__ void inproj_pe(const float* __restrict__ bs, const float* __restrict__ W,
                          const float* __restrict__ b, float* __restrict__ out)
{
    int idx = blockIdx.x * blockDim.x + threadIdx.x;
    if (idx >= NTOK * DD) return;
    int row = idx / DD;
    int col = idx - row * DD;
    float s = 0.0f;
    const float* xr = bs + (size_t)row * DIN;
#pragma unroll 2
    for (int k = 0; k < DIN; k++)
        s = fmaf(xr[k], W[(size_t)k * DD + col], s);
    s = __fadd_rn(s, b[col]);

    int pos = row & (SS - 1);
    int i = col >> 1;
    const float c32 = (float)(-9.210340371976184 / 512.0);
    float t   = __fmul_rn((float)(2 * i), c32);
    float dv  = xla_expf(t);
    float ang = __fmul_rn((float)pos, dv);
    float pe  = (col & 1) ? (float)cos((double)ang)
                          : (float)sin((double)ang);
    out[idx] = __fadd_rn(s, pe);
}

// ---------------------------------------------------------------------------
// Output projection (unchanged)
// ---------------------------------------------------------------------------
__global__ void outproj(const float* __restrict__ X, const float* __restrict__ W,
                        const float* __restrict__ b, float* __restrict__ out)
{
    int idx = blockIdx.x * blockDim.x + threadIdx.x;
    if (idx >= NTOK * DIN) return;
    int row = idx / DIN;
    int col = idx - row * DIN;
    float s = 0.0f;
    const float* xr = X + (size_t)row * DD;
#pragma unroll 4
    for (int k = 0; k < DD; k++)
        s = fmaf(xr[k], W[(size_t)k * DIN + col], s);
    out[idx] = __fadd_rn(s, b[col]);
}

// ---------------------------------------------------------------------------
// LayerNorm(x + a) in place. Block-tree reductions (order proven flip-neutral);
// same elementwise ops + CR 1/sqrt as the passing kernel.
// ---------------------------------------------------------------------------
__global__ __launch_bounds__(128) void ln_add(
    float* __restrict__ x, const float* __restrict__ a,
    const float* __restrict__ g, const float* __restrict__ bb)
{
    const int row = blockIdx.x;
    const int tid = threadIdx.x;
    __shared__ float v[DD];
    __shared__ float red[128];

    float s = 0.0f;
#pragma unroll
    for (int i = 0; i < 4; i++) {
        int c = tid + i * 128;
        float t = __fadd_rn(x[(size_t)row * DD + c], a[(size_t)row * DD + c]);
        v[c] = t;
        s = __fadd_rn(s, t);
    }
    red[tid] = s;
    __syncthreads();
    for (int o = 64; o > 0; o >>= 1) {
        if (tid < o) red[tid] = __fadd_rn(red[tid], red[tid + o]);
        __syncthreads();
    }
    float mu = __fmul_rn(red[0], 1.0f / DD);
    __syncthreads();

    s = 0.0f;
#pragma unroll
    for (int i = 0; i < 4; i++) {
        int c = tid + i * 128;
        float d = __fsub_rn(v[c], mu);
        s = __fadd_rn(s, __fmul_rn(d, d));
    }
    red[tid] = s;
    __syncthreads();
    for (int o = 64; o > 0; o >>= 1) {
        if (tid < o) red[tid] = __fadd_rn(red[tid], red[tid + o]);
        __syncthreads();
    }
    float var = __fmul_rn(red[0], 1.0f / DD);
    float rs = __fdiv_rn(1.0f, __fsqrt_rn(__fadd_rn(var, 1e-5f)));

#pragma unroll
    for (int i = 0; i < 4; i++) {
        int c = tid + i * 128;
        float t = __fmul_rn(__fmul_rn(__fsub_rn(v[c], mu), rs), g[c]);
        x[(size_t)row * DD + c] = __fadd_rn(t, bb[c]);
    }
}

// ---------------------------------------------------------------------------
// misc
// ---------------------------------------------------------------------------
__global__ void zero_kernel(float* __restrict__ p, int n)
{
    int i = blockIdx.x * blockDim.x + threadIdx.x;
    if (i < n) p[i] = 0.0f;
}
__global__ void copy_kernel(float* __restrict__ dst, const float* __restrict__ src, int n)
{
    int i = blockIdx.x * blockDim.x + threadIdx.x;
    if (i < n) dst[i] = src[i];
}

// ---------------------------------------------------------------------------
// One residual-VQ stage (unchanged — frozen numerics)
// ---------------------------------------------------------------------------
__global__ __launch_bounds__(256) void vq_step(
    const float* __restrict__ cb, float* __restrict__ r,
    float* __restrict__ qout, float* __restrict__ lossp, int qi)
{
    int warp = (blockIdx.x * blockDim.x + threadIdx.x) >> 5;
    int lane = threadIdx.x & 31;
    if (warp >= NTOK * GG) return;
    int t = warp >> 5;
    int g = warp & 31;

    float rv[DG_];
    float* rp = r + (size_t)t * DD + g * DG_;
#pragma unroll
    for (int d = 0; d < DG_; d++) rv[d] = rp[d];

    float s_r = 0.0f;
#pragma unroll
    for (int d = 0; d < DG_; d++)
        s_r = __fadd_rn(s_r, __fmul_rn(rv[d], rv[d]));

    const float* cbase = cb + ((size_t)(g * NQ_ + qi)) * KK_ * DG_;

    float best = 3.4e38f;
    int bi = 0;
    for (int i = 0; i < KK_ / 32; i++) {
        int k = lane + i * 32;
        const float* c = cbase + (size_t)k * DG_;
        float cv[DG_];
        float4 t0 = *(const float4*)(c + 0);
        float4 t1 = *(const float4*)(c + 4);
        float4 t2 = *(const float4*)(c + 8);
        float4 t3 = *(const float4*)(c + 12);
        cv[0]=t0.x; cv[1]=t0.y; cv[2]=t0.z; cv[3]=t0.w;
        cv[4]=t1.x; cv[5]=t1.y; cv[6]=t1.z; cv[7]=t1.w;
        cv[8]=t2.x; cv[9]=t2.y; cv[10]=t2.z; cv[11]=t2.w;
        cv[12]=t3.x; cv[13]=t3.y; cv[14]=t3.z; cv[15]=t3.w;

        float dot = 0.0f;
#pragma unroll
        for (int d = 0; d < DG_; d++)
            dot = fmaf(rv[d], cv[d], dot);

        float scb = 0.0f;
#pragma unroll
        for (int d = 0; d < DG_; d++)
            scb = __fadd_rn(scb, __fmul_rn(cv[d], cv[d]));

        float d2 = __fadd_rn(__fsub_rn(s_r, __fmul_rn(2.0f, dot)), scb);
        if (d2 < best) { best = d2; bi = k; }
    }
#pragma unroll
    for (int off = 16; off > 0; off >>= 1) {
        float ob = __shfl_xor_sync(0xffffffffu, best, off);
        int   oi = __shfl_xor_sync(0xffffffffu, bi, off);
        if (ob < best || (ob == best && oi < bi)) { best = ob; bi = oi; }
    }

    const float* c = cbase + (size_t)bi * DG_;
    float err = 0.0f;
    if (lane < DG_) {
        float cv  = c[lane];
        float rvv = rv[lane];
        float df  = __fsub_rn(cv, rvv);
        err = __fmul_rn(df, df);
        size_t qidx = (size_t)t * DD + g * DG_ + lane;
        float qold = qout[qidx];
        qout[qidx] = __fadd_rn(__fadd_rn(qold, rvv), df);
        rp[lane] = __fsub_rn(rvv, cv);
    }
#pragma unroll
    for (int off = 8; off > 0; off >>= 1)
        err += __shfl_xor_sync(0xffffffffu, err, off);
    if (lane == 0) lossp[warp] += err;
}

// ---------------------------------------------------------------------------
// Deterministic loss reduce (unchanged)
// ---------------------------------------------------------------------------
__global__ void loss_reduce(const float* __restrict__ lp, float* __restrict__ out)
{
    __shared__ float red[256];
    int tid = threadIdx.x;
    float s = 0.0f;
    for (int i = tid; i < NTOK * GG; i += 256) s += lp[i];
    red[tid] = s;
    __syncthreads();
    for (int o = 128; o > 0; o >>= 1) {
        if (tid < o) red[tid] += red[tid + o];
        __syncthreads();
    }
    if (tid == 0)
        out[0] = 0.1f * red[0] / 2097152.0f;
}

// ---------------------------------------------------------------------------
// Host orchestration
// ---------------------------------------------------------------------------
struct BlockParams {
    const float *qkv_w, *qkv_b, *out_w, *out_b, *ln1_g, *ln1_b;
    const float *ff1_w, *ff1_b, *ff2_w, *ff2_b, *ln2_g, *ln2_b;
};

static void run_block(float* X, float* QKV, float* ATT, float* TMP, float* FFH,
                      float* SC, const BlockParams& p)
{
    for (int i = 0; i < NLAYERS; i++) {
        sgemm_n128<0,0,1><<<dim3(12, 32), 256>>>(X, p.qkv_w + (size_t)i * DD * 3 * DD,
                                                 p.qkv_b + (size_t)i * 3 * DD, QKV,
                                                 NTOK, 3 * DD, DD, DD);
        attn_scores<<<dim3(8, 8, 32), 256>>>(QKV, SC);
        attn_softmax<<<dim3(SS, BB * HH), 256>>>(SC);
        attn_av<<<dim3(8, BB * HH), 256>>>(SC, QKV, ATT);
        sgemm_n64<0,0,1><<<dim3(8, 32), 256>>>(ATT, p.out_w + (size_t)i * DD * DD,
                                               p.out_b + (size_t)i * DD, TMP,
                                               NTOK, DD, DD, DD);
        ln_add<<<NTOK, 128>>>(X, TMP, p.ln1_g + (size_t)i * DD, p.ln1_b + (size_t)i * DD);
        sgemm_n128<1,0,1><<<dim3(16, 32), 256>>>(X, p.ff1_w + (size_t)i * DD * FF_,
                                                 p.ff1_b + (size_t)i * FF_, FFH,
                                                 NTOK, FF_, DD, DD);
        // ff2: Eigen kc panels of 1024: C = ((p1 + p2) + bias)
        sgemm_n64<0,0,0><<<dim3(8, 32), 256>>>(FFH, p.ff2_w + (size_t)i * FF_ * DD,
                                               p.ff2_b + (size_t)i * DD, TMP,
                                               NTOK, DD, 1024, FF_);
        sgemm_n64<0,1,1><<<dim3(8, 32), 256>>>(FFH + 1024,
                                               p.ff2_w + (size_t)i * FF_ * DD + (size_t)1024 * DD,
                                               p.ff2_b + (size_t)i * DD, TMP,
                                               NTOK, DD, 1024, FF_);
        ln_add<<<NTOK, 128>>>(X, TMP, p.ln2_g + (size_t)i * DD, p.ln2_b + (size_t)i * DD);
    }
}

extern "C" void kernel_launch(void* const* d_in, const int* in_sizes, int n_in,
                              void* d_out, int out_size)
{
    const float* blendshapes = (const float*)d_in[0];
    const float* w_in  = (const float*)d_in[1];
    const float* b_in  = (const float*)d_in[2];

    BlockParams enc, dec;
    enc.qkv_w = (const float*)d_in[3];  enc.qkv_b = (const float*)d_in[4];
    enc.out_w = (const float*)d_in[5];  enc.out_b = (const float*)d_in[6];
    enc.ln1_g = (const float*)d_in[7];  enc.ln1_b = (const float*)d_in[8];
    enc.ff1_w = (const float*)d_in[9];  enc.ff1_b = (const float*)d_in[10];
    enc.ff2_w = (const float*)d_in[11]; enc.ff2_b = (const float*)d_in[12];
    enc.ln2_g = (const float*)d_in[13]; enc.ln2_b = (const float*)d_in[14];
    dec.qkv_w = (const float*)d_in[15]; dec.qkv_b = (const float*)d_in[16];
    dec.out_w = (const float*)d_in[17]; dec.out_b = (const float*)d_in[18];
    dec.ln1_g = (const float*)d_in[19]; dec.ln1_b = (const float*)d_in[20];
    dec.ff1_w = (const float*)d_in[21]; dec.ff1_b = (const float*)d_in[22];
    dec.ff2_w = (const float*)d_in[23]; dec.ff2_b = (const float*)d_in[24];
    dec.ln2_g = (const float*)d_in[25]; dec.ln2_b = (const float*)d_in[26];
    const float* codebooks = (const float*)d_in[27];
    const float* w_out = (const float*)d_in[28];
    const float* b_out = (const float*)d_in[29];

    float *X, *QKV, *ATT, *TMP, *FFH, *VQR, *QOUT, *LOSSP, *SC;
    cudaGetSymbolAddress((void**)&X,    g_X);
    cudaGetSymbolAddress((void**)&QKV,  g_QKV);
    cudaGetSymbolAddress((void**)&ATT,  g_ATT);
    cudaGetSymbolAddress((void**)&TMP,  g_TMP);
    cudaGetSymbolAddress((void**)&FFH,  g_FFH);
    cudaGetSymbolAddress((void**)&VQR,  g_VQR);
    cudaGetSymbolAddress((void**)&QOUT, g_QOUT);
    cudaGetSymbolAddress((void**)&LOSSP,g_LOSSP);
    cudaGetSymbolAddress((void**)&SC,   g_SC);

    // 1. Input projection + positional encoding
    inproj_pe<<<(NTOK * DD + 255) / 256, 256>>>(blendshapes, w_in, b_in, X);

    // 2. Encoder
    run_block(X, QKV, ATT, TMP, FFH, SC, enc);

    // 3. Grouped residual VQ
    copy_kernel<<<(NTOK * DD + 255) / 256, 256>>>(VQR, X, NTOK * DD);
    zero_kernel<<<(NTOK * DD + 255) / 256, 256>>>(QOUT, NTOK * DD);
    zero_kernel<<<(NTOK * GG + 255) / 256, 256>>>(LOSSP, NTOK * GG);
    for (int qi = 0; qi < NQ_; qi++)
        vq_step<<<(NTOK * GG * 32 + 255) / 256, 256>>>(codebooks, VQR, QOUT, LOSSP, qi);

    // 4. Decoder
    run_block(QOUT, QKV, ATT, TMP, FFH, SC, dec);

    // 5. Output projection + loss
    float* out = (float*)d_out;
    outproj<<<(NTOK * DIN + 127) / 128, 128>>>(QOUT, w_out, b_out, out);
    loss_reduce<<<1, 256>>>(LOSSP, out + (out_size - 1));
}